// round 3
// baseline (speedup 1.0000x reference)
#include <cuda_runtime.h>
#include <cuda_bf16.h>

// TriplePairwiseCEFocalLoss — B=8192 rows, S=4096 cols.
// per_sample[b] = mean over negatives j of (1-pt)^2 * softplus(scores[b,j]-pos)
//   pos = scores[b, tail[b]], pt = 1/(1+e^(scores-pos)) clipped to [1e-7, 1-1e-7]
//   negatives: mask[b,j]==1 AND j != head[b] AND j != tail[b]
// output = sum_b per_sample[b] / B
//
// Single fused kernel: warp-per-row streaming (256 MiB, HBM-bound),
// per-CTA partial in smem, last-CTA-done final reduction (deterministic:
// int-atomic gate, fixed summation order, no float atomics).

#define BB 8192
#define SS 4096
#define S4 (SS / 4)          // 1024 float4 per row
#define THREADS 256
#define WARPS_PER_CTA (THREADS / 32)
#define NCTAS (BB / WARPS_PER_CTA)   // 1024

__device__ float    g_partial[NCTAS];
__device__ unsigned g_count = 0;

__device__ __forceinline__ float focal_elem(float sc, float pos) {
    float x  = sc - pos;
    float ex = __expf(x);          // EX2
    float w  = ex + 1.0f;
    float sp = __logf(w);          // LG2  == softplus(x) == -logpt
    float pt;
    asm("rcp.approx.f32 %0, %1;" : "=f"(pt) : "f"(w));   // RCP: pt = 1/(1+e^x)
    pt = fminf(fmaxf(pt, 1e-7f), 1.0f - 1e-7f);
    float om = 1.0f - pt;
    return om * om * sp;           // focal loss (ALPHA=1, GAMMA=2)
}

__global__ __launch_bounds__(THREADS, 8)
void focal_fused_kernel(const float* __restrict__ scores,
                        const int*   __restrict__ head_position,
                        const int*   __restrict__ tail_position,
                        const int*   __restrict__ score_mask,
                        float* __restrict__ out) {
    __shared__ float sh_warp[WARPS_PER_CTA];

    const int warpid = threadIdx.x >> 5;
    const int lane   = threadIdx.x & 31;
    const int row    = blockIdx.x * WARPS_PER_CTA + warpid;

    const float* __restrict__ srow = scores     + (size_t)row * SS;
    const int*   __restrict__ mrow = score_mask + (size_t)row * SS;
    const int h = __ldg(head_position + row);
    const int t = __ldg(tail_position + row);
    const float pos = __ldg(srow + t);    // broadcast load

    float fs0 = 0.0f, fs1 = 0.0f;
    int   cnt = 0;

    const float4* __restrict__ s4 = (const float4*)srow;
    const int4*   __restrict__ m4 = (const int4*)mrow;

    #pragma unroll 4
    for (int i = lane; i < S4; i += 32) {
        float4 sc = __ldg(s4 + i);
        int4   mk = __ldg(m4 + i);
        int jb = i * 4;
        bool n0 = (mk.x == 1) && (jb + 0 != h) && (jb + 0 != t);
        bool n1 = (mk.y == 1) && (jb + 1 != h) && (jb + 1 != t);
        bool n2 = (mk.z == 1) && (jb + 2 != h) && (jb + 2 != t);
        bool n3 = (mk.w == 1) && (jb + 3 != h) && (jb + 3 != t);
        if (n0) { fs0 += focal_elem(sc.x, pos); cnt++; }
        if (n1) { fs1 += focal_elem(sc.y, pos); cnt++; }
        if (n2) { fs0 += focal_elem(sc.z, pos); cnt++; }
        if (n3) { fs1 += focal_elem(sc.w, pos); cnt++; }
    }

    float fs = fs0 + fs1;
    float cs = (float)cnt;

    // warp tree-reduce (shfl only)
    #pragma unroll
    for (int off = 16; off > 0; off >>= 1) {
        fs += __shfl_xor_sync(0xffffffffu, fs, off);
        cs += __shfl_xor_sync(0xffffffffu, cs, off);
    }

    if (lane == 0)
        sh_warp[warpid] = (cs > 0.5f) ? (fs / cs) : 0.0f;   // per-row mean
    __syncthreads();

    // thread 0 sums this CTA's 8 rows in fixed order -> partial
    __shared__ bool sh_is_last;
    if (threadIdx.x == 0) {
        float p = 0.0f;
        #pragma unroll
        for (int wgi = 0; wgi < WARPS_PER_CTA; wgi++) p += sh_warp[wgi];
        g_partial[blockIdx.x] = p;
        __threadfence();
        unsigned prev = atomicAdd(&g_count, 1u);
        sh_is_last = (prev == (unsigned)(gridDim.x - 1));
    }
    __syncthreads();

    // last CTA: deterministic final reduction over 1024 partials (L2-hot)
    if (sh_is_last) {
        __threadfence();   // acquire all partials
        float s = 0.0f;
        #pragma unroll
        for (int k = 0; k < NCTAS / THREADS; k++)          // 4 per thread
            s += __ldcg(&g_partial[threadIdx.x + k * THREADS]);
        // block reduce: shfl within warp, then smem across 8 warps
        #pragma unroll
        for (int off = 16; off > 0; off >>= 1)
            s += __shfl_xor_sync(0xffffffffu, s, off);
        __shared__ float sh_fin[WARPS_PER_CTA];
        if (lane == 0) sh_fin[warpid] = s;
        __syncthreads();
        if (threadIdx.x == 0) {
            float tot = 0.0f;
            #pragma unroll
            for (int wgi = 0; wgi < WARPS_PER_CTA; wgi++) tot += sh_fin[wgi];
            out[0] = tot * (1.0f / (float)BB);
            g_count = 0;   // reset for next graph replay
        }
    }
}

extern "C" void kernel_launch(void* const* d_in, const int* in_sizes, int n_in,
                              void* d_out, int out_size) {
    const float* scores = (const float*)d_in[0];
    const int*   head   = (const int*)d_in[1];
    const int*   tail   = (const int*)d_in[2];
    const int*   mask   = (const int*)d_in[3];
    float* out = (float*)d_out;

    focal_fused_kernel<<<NCTAS, THREADS>>>(scores, head, tail, mask, out);
}

// round 15
// speedup vs baseline: 1.1282x; 1.1282x over previous
#include <cuda_runtime.h>
#include <cuda_bf16.h>

// TriplePairwiseCEFocalLoss — B=8192 rows, S=4096 cols.
// per_sample[b] = mean over negatives j of (1-pt)^2 * softplus(scores[b,j]-pos)
//   pos = scores[b, tail[b]], pt = sigmoid(pos - scores[b,j])
//   negatives: mask[b,j]==1 AND j != head[b] AND j != tail[b]
// output = sum_b per_sample[b] / B
//
// R4 change-set (12th submission; broker timeouts, never measured):
// branchless mask-weighted inner loop (mask ∈ {0,1} → weight = (float)mask,
// no index compares; h/t exclusion done as a per-row post-fixup on lane 0).
// __launch_bounds__(256,4) to allow 64 regs → 2x MLP with unroll 8.
// Fused deterministic last-CTA-done final reduction.

#define BB 8192
#define SS 4096
#define S4 (SS / 4)          // 1024 float4 per row
#define THREADS 256
#define WARPS_PER_CTA (THREADS / 32)
#define NCTAS (BB / WARPS_PER_CTA)   // 1024

__device__ float    g_partial[NCTAS];
__device__ unsigned g_count = 0;

// focal loss for pair (sc vs pos): (1-pt)^2 * softplus(sc-pos), pt = 1/(1+e^(sc-pos))
// clip omitted: binds only for |sc-pos| > 16.1; data is N(0,1) diffs (|x| <~ 11).
__device__ __forceinline__ float focal_elem(float sc, float pos) {
    float x  = sc - pos;
    float ex = __expf(x);          // EX2
    float w  = ex + 1.0f;
    float sp = __logf(w);          // LG2  == softplus(x)
    float r;
    asm("rcp.approx.f32 %0, %1;" : "=f"(r) : "f"(w));   // 1/(1+e^x)
    float om = ex * r;             // 1 - pt  (stable form, no cancellation)
    return om * om * sp;
}

__global__ __launch_bounds__(THREADS, 4)
void focal_fused_kernel(const float* __restrict__ scores,
                        const int*   __restrict__ head_position,
                        const int*   __restrict__ tail_position,
                        const int*   __restrict__ score_mask,
                        float* __restrict__ out) {
    __shared__ float sh_warp[WARPS_PER_CTA];

    const int warpid = threadIdx.x >> 5;
    const int lane   = threadIdx.x & 31;
    const int row    = blockIdx.x * WARPS_PER_CTA + warpid;

    const float* __restrict__ srow = scores     + (size_t)row * SS;
    const int*   __restrict__ mrow = score_mask + (size_t)row * SS;
    const int h = __ldg(head_position + row);
    const int t = __ldg(tail_position + row);
    const float pos = __ldg(srow + t);    // broadcast load

    float fs0 = 0.0f, fs1 = 0.0f;
    int   cnt = 0;

    const float4* __restrict__ s4 = (const float4*)srow;
    const int4*   __restrict__ m4 = (const int4*)mrow;

    // Branchless: weight = (float)mask (mask ∈ {0,1}); h/t fixed up after loop.
    #pragma unroll 8
    for (int i = lane; i < S4; i += 32) {
        float4 sc = __ldg(s4 + i);
        int4   mk = __ldg(m4 + i);
        fs0 = fmaf((float)mk.x, focal_elem(sc.x, pos), fs0);
        fs1 = fmaf((float)mk.y, focal_elem(sc.y, pos), fs1);
        fs0 = fmaf((float)mk.z, focal_elem(sc.z, pos), fs0);
        fs1 = fmaf((float)mk.w, focal_elem(sc.w, pos), fs1);
        cnt += mk.x + mk.y + mk.z + mk.w;
    }

    float fs = fs0 + fs1;
    float cs = (float)cnt;

    // warp tree-reduce (shfl only)
    #pragma unroll
    for (int off = 16; off > 0; off >>= 1) {
        fs += __shfl_xor_sync(0xffffffffu, fs, off);
        cs += __shfl_xor_sync(0xffffffffu, cs, off);
    }

    if (lane == 0) {
        // h/t exclusion fixup: subtract wrongly-included contributions (L2-hot loads)
        int mh = __ldg(mrow + h);
        if (mh == 1) { fs -= focal_elem(__ldg(srow + h), pos); cs -= 1.0f; }
        if (t != h) {
            int mt = __ldg(mrow + t);
            if (mt == 1) { fs -= focal_elem(pos, pos); cs -= 1.0f; }
        }
        sh_warp[warpid] = (cs > 0.5f) ? (fs / cs) : 0.0f;   // per-row mean
    }
    __syncthreads();

    // thread 0 sums this CTA's 8 rows in fixed order -> partial
    __shared__ bool sh_is_last;
    if (threadIdx.x == 0) {
        float p = 0.0f;
        #pragma unroll
        for (int wgi = 0; wgi < WARPS_PER_CTA; wgi++) p += sh_warp[wgi];
        g_partial[blockIdx.x] = p;
        __threadfence();
        unsigned prev = atomicAdd(&g_count, 1u);
        sh_is_last = (prev == (unsigned)(gridDim.x - 1));
    }
    __syncthreads();

    // last CTA: deterministic final reduction over 1024 partials (L2-hot)
    if (sh_is_last) {
        __threadfence();   // acquire all partials
        float s = 0.0f;
        #pragma unroll
        for (int k = 0; k < NCTAS / THREADS; k++)          // 4 per thread
            s += __ldcg(&g_partial[threadIdx.x + k * THREADS]);
        #pragma unroll
        for (int off = 16; off > 0; off >>= 1)
            s += __shfl_xor_sync(0xffffffffu, s, off);
        __shared__ float sh_fin[WARPS_PER_CTA];
        if (lane == 0) sh_fin[warpid] = s;
        __syncthreads();
        if (threadIdx.x == 0) {
            float tot = 0.0f;
            #pragma unroll
            for (int wgi = 0; wgi < WARPS_PER_CTA; wgi++) tot += sh_fin[wgi];
            out[0] = tot * (1.0f / (float)BB);
            g_count = 0;   // reset for next graph replay
        }
    }
}

extern "C" void kernel_launch(void* const* d_in, const int* in_sizes, int n_in,
                              void* d_out, int out_size) {
    const float* scores = (const float*)d_in[0];
    const int*   head   = (const int*)d_in[1];
    const int*   tail   = (const int*)d_in[2];
    const int*   mask   = (const int*)d_in[3];
    float* out = (float*)d_out;

    focal_fused_kernel<<<NCTAS, THREADS>>>(scores, head, tail, mask, out);
}